// round 10
// baseline (speedup 1.0000x reference)
#include <cuda_runtime.h>
#include <math.h>
#include <stdint.h>

#define T_STEPS 1024
#define BATCH   64
#define VDIM    256
#define HIDDEN  512
#define CPB     64                 // columns per CTA
#define BG      2                  // batches per chain group
#define CBLKS   8                  // CTAs per group
#define GROUPS  32                 // independent chains (2 per CTA)
#define NB      128                // CTAs (16 pairs x 8)
#define RT      256
#define CHPAD   36                 // padded 32-float k-chunk stride
#define BHSTR   (16 * CHPAD)       // per-batch h stride = 576 floats
#define PSTR    21                 // partials row stride
#define REC_SMEM (120 * 1024)      // force 1 CTA/SM

// Scratch (device globals: allocation APIs are forbidden)
__device__ float g_P [(size_t)T_STEPS * BATCH * HIDDEN];
__device__ float g_S0[(size_t)T_STEPS * BATCH * HIDDEN];
__device__ float g_Hbuf[2][GROUPS][BG * HIDDEN];

struct PadU { unsigned v; unsigned pad[63]; };
__device__ PadU g_count[GROUPS];
__device__ PadU g_gen[GROUPS];

#define FMA2(acc, w, h) \
    asm("fma.rn.f32x2 %0, %1, %2, %0;" : "+l"(acc) : "l"(w), "l"(h))
#define PACKF2(d, x) \
    asm("mov.b64 %0, {%1, %1};" : "=l"(d) : "f"(x))

__device__ __forceinline__ unsigned smem_u32(const void* p) {
    return (unsigned)__cvta_generic_to_shared(p);
}
__device__ __forceinline__ void cp16(unsigned s, const void* g) {
    asm volatile("cp.async.cg.shared.global [%0], [%1], 16;" :: "r"(s), "l"(g));
}

// ---------------------------------------------------------------------------
// GEMM (f32x2): C[m][n] = sum_k A[m][k]*W[n*ldw+k] + bias[n]
// ---------------------------------------------------------------------------
__global__ __launch_bounds__(256) void gemm_awt(
    const float* __restrict__ A, const float* __restrict__ W,
    const float* __restrict__ bias, float* __restrict__ C,
    int K, int ldw)
{
    __shared__ float As[8][128];
    __shared__ float Ws[8][128];

    const int tid = threadIdx.x;
    const int m0 = blockIdx.y * 128;
    const int n0 = blockIdx.x * 128;
    const int tx = tid & 15;
    const int ty = tid >> 4;
    const int rowL = tid >> 1;
    const int colL = (tid & 1) * 4;

    const float* Ag = A + (size_t)(m0 + rowL) * K + colL;
    const float* Wg = W + (size_t)(n0 + rowL) * ldw + colL;

    long long accp[8][4];
#pragma unroll
    for (int i = 0; i < 8; ++i)
#pragma unroll
        for (int jp = 0; jp < 4; ++jp) accp[i][jp] = 0;

    float4 av = *(const float4*)(Ag);
    float4 wv = *(const float4*)(Wg);

    for (int k0 = 0; k0 < K; k0 += 8) {
        __syncthreads();
        As[colL + 0][rowL] = av.x; As[colL + 1][rowL] = av.y;
        As[colL + 2][rowL] = av.z; As[colL + 3][rowL] = av.w;
        Ws[colL + 0][rowL] = wv.x; Ws[colL + 1][rowL] = wv.y;
        Ws[colL + 2][rowL] = wv.z; Ws[colL + 3][rowL] = wv.w;
        __syncthreads();
        if (k0 + 8 < K) {
            av = *(const float4*)(Ag + k0 + 8);
            wv = *(const float4*)(Wg + k0 + 8);
        }
#pragma unroll
        for (int k = 0; k < 8; ++k) {
            float4 a0 = *(const float4*)&As[k][ty * 8];
            float4 a1 = *(const float4*)&As[k][ty * 8 + 4];
            longlong2 b01 = *(const longlong2*)&Ws[k][tx * 8];
            longlong2 b23 = *(const longlong2*)&Ws[k][tx * 8 + 4];
            float a[8] = {a0.x, a0.y, a0.z, a0.w, a1.x, a1.y, a1.z, a1.w};
#pragma unroll
            for (int i = 0; i < 8; ++i) {
                long long a2; PACKF2(a2, a[i]);
                FMA2(accp[i][0], a2, b01.x);
                FMA2(accp[i][1], a2, b01.y);
                FMA2(accp[i][2], a2, b23.x);
                FMA2(accp[i][3], a2, b23.y);
            }
        }
    }

    float bn[8];
#pragma unroll
    for (int j = 0; j < 8; ++j) bn[j] = bias[n0 + tx * 8 + j];

    float* Cp = C + (size_t)(m0 + ty * 8) * HIDDEN + n0 + tx * 8;
#pragma unroll
    for (int i = 0; i < 8; ++i) {
        float4 v0, v1;
        float2 f0 = *reinterpret_cast<float2*>(&accp[i][0]);
        float2 f1 = *reinterpret_cast<float2*>(&accp[i][1]);
        float2 f2 = *reinterpret_cast<float2*>(&accp[i][2]);
        float2 f3 = *reinterpret_cast<float2*>(&accp[i][3]);
        v0.x = f0.x + bn[0]; v0.y = f0.y + bn[1];
        v0.z = f1.x + bn[2]; v0.w = f1.y + bn[3];
        v1.x = f2.x + bn[4]; v1.y = f2.y + bn[5];
        v1.z = f3.x + bn[6]; v1.w = f3.y + bn[7];
        *(float4*)(Cp + (size_t)i * HIDDEN)     = v0;
        *(float4*)(Cp + (size_t)i * HIDDEN + 4) = v1;
    }
}

// ---------------------------------------------------------------------------
// Recurrence helpers
// ---------------------------------------------------------------------------
__device__ __forceinline__ void chain_partials(
    const float* __restrict__ Hs, const longlong2 (&wr)[4][8],
    int kc, int jg, float* __restrict__ Ps)
{
    long long acc[4][2];
#pragma unroll
    for (int c = 0; c < 4; ++c) { acc[c][0] = 0; acc[c][1] = 0; }
    const float* hc = Hs + kc * CHPAD;
#pragma unroll
    for (int i = 0; i < 8; ++i) {
        union { float4 f; longlong2 l; } u0, u1;
        u0.f = *(const float4*)(hc + i * 4);
        u1.f = *(const float4*)(hc + BHSTR + i * 4);
#pragma unroll
        for (int c = 0; c < 4; ++c) {
            longlong2 w = wr[c][i];
            FMA2(acc[c][0], w.x, u0.l.x); FMA2(acc[c][0], w.y, u0.l.y);
            FMA2(acc[c][1], w.x, u1.l.x); FMA2(acc[c][1], w.y, u1.l.y);
        }
    }
#pragma unroll
    for (int c = 0; c < 4; ++c)
#pragma unroll
        for (int b = 0; b < 2; ++b) {
            float2 f = *reinterpret_cast<float2*>(&acc[c][b]);
            Ps[(b * 64 + jg * 4 + c) * PSTR + kc] = f.x + f.y;
        }
}

__device__ __forceinline__ void group_arrive(int grp, unsigned gen)
{
    unsigned tk = atomicAdd(&g_count[grp].v, 1u);
    if (tk == CBLKS - 1u) {
        *(volatile unsigned*)&g_count[grp].v = 0u;
        __threadfence();
        *(volatile unsigned*)&g_gen[grp].v = gen + 1u;
    }
}
__device__ __forceinline__ void group_wait(int grp, unsigned gen)
{
    while (*(volatile unsigned*)&g_gen[grp].v == gen) { }
    __threadfence();
}

// ---------------------------------------------------------------------------
// Persistent recurrence, dual-chain:
//   CTA serves 2 independent batch groups (A,B) with SHARED weight registers.
//   A's exchange latency hides behind B's compute and vice versa.
// ---------------------------------------------------------------------------
__global__ __launch_bounds__(RT, 1) void rnn_rec(
    const float* __restrict__ P,
    const float* __restrict__ Wfull, int ldw, int koff,
    const float* __restrict__ h0,
    float* __restrict__ states,
    float* __restrict__ last)
{
    extern __shared__ float sh[];
    float* HsA = sh;                       // [2][BHSTR]
    float* HsB = sh + 2 * BHSTR;
    float* PsA = sh + 4 * BHSTR;           // [128][PSTR]
    float* PsB = PsA + 128 * PSTR;

    const int tid  = threadIdx.x;
    const int cblk = blockIdx.x & (CBLKS - 1);
    const int pair = blockIdx.x >> 3;
    const int grpA = pair * 2, grpB = pair * 2 + 1;
    const int j0   = cblk * CPB;
    const int kc   = tid & 15;
    const int jg   = tid >> 4;
    const int rb   = tid >> 6;             // valid for tid<128: 0..1
    const int rcol = tid & 63;
    const int rj   = j0 + rcol;

    // Shared weight registers for both chains.
    union LLF { float4 f; longlong2 l; };
    longlong2 wr[4][8];
#pragma unroll
    for (int c = 0; c < 4; ++c) {
        const float* wp = Wfull + (size_t)(j0 + jg * 4 + c) * ldw + koff + kc * 32;
#pragma unroll
        for (int i = 0; i < 8; ++i) {
            LLF u; u.f = *(const float4*)(wp + i * 4);
            wr[c][i] = u.l;
        }
    }

    // Stage h0 for both chains (chunk-padded layout).
    for (int i = tid; i < 2 * BG * HIDDEN; i += RT) {
        int chain = i >> 10, b = (i >> 9) & 1, k = i & 511;
        float* Hs = chain ? HsB : HsA;
        int grp = chain ? grpB : grpA;
        Hs[b * BHSTR + (k >> 5) * CHPAD + (k & 31)] =
            h0[(size_t)(grp * BG + b) * HIDDEN + k];
    }
    __syncthreads();

    unsigned genA = *(volatile unsigned*)&g_gen[grpA].v;
    unsigned genB = *(volatile unsigned*)&g_gen[grpB].v;

    float pA = 0.f, pB = 0.f;
    if (tid < 128) {
        pA = P[((size_t)0 * BATCH + grpA * BG + rb) * HIDDEN + rj];
        pB = P[((size_t)0 * BATCH + grpB * BG + rb) * HIDDEN + rj];
    }

    for (int t = 0; t < T_STEPS; ++t) {
        const bool lastStep = (t == T_STEPS - 1);

        // ---- chain A: compute + publish ----
        chain_partials(HsA, wr, kc, jg, PsA);
        __syncthreads();
        if (tid < 128) {
            float s = 0.f;
            const float* pr = PsA + tid * PSTR;
#pragma unroll
            for (int i = 0; i < 16; ++i) s += pr[i];
            float hv = tanhf(pA + s);
            states[((size_t)t * BATCH + grpA * BG + rb) * HIDDEN + rj] = hv;
            if (lastStep) last[(size_t)(grpA * BG + rb) * HIDDEN + rj] = hv;
            else          g_Hbuf[t & 1][grpA][rb * HIDDEN + rj] = hv;
        }
        if (!lastStep) __threadfence();
        __syncthreads();
        if (!lastStep && tid == 0) group_arrive(grpA, genA);

        // ---- chain B: compute + publish ----
        chain_partials(HsB, wr, kc, jg, PsB);
        __syncthreads();
        if (tid < 128) {
            float s = 0.f;
            const float* pr = PsB + tid * PSTR;
#pragma unroll
            for (int i = 0; i < 16; ++i) s += pr[i];
            float hv = tanhf(pB + s);
            states[((size_t)t * BATCH + grpB * BG + rb) * HIDDEN + rj] = hv;
            if (lastStep) last[(size_t)(grpB * BG + rb) * HIDDEN + rj] = hv;
            else          g_Hbuf[t & 1][grpB][rb * HIDDEN + rj] = hv;
        }
        if (lastStep) break;
        __threadfence();
        __syncthreads();
        if (tid == 0) group_arrive(grpB, genB);

        // Prefetch next step's P while exchanges are in flight.
        if (tid < 128) {
            pA = P[((size_t)(t + 1) * BATCH + grpA * BG + rb) * HIDDEN + rj];
            pB = P[((size_t)(t + 1) * BATCH + grpB * BG + rb) * HIDDEN + rj];
        }

        // ---- wait + restage A ----
        if (tid == 0) group_wait(grpA, genA);
        __syncthreads();
        {
            int b = tid >> 7, k = (tid & 127) << 2;
            const float* src = &g_Hbuf[t & 1][grpA][0];
            cp16(smem_u32(HsA + b * BHSTR + (k >> 5) * CHPAD + (k & 31)),
                 src + b * HIDDEN + k);
            asm volatile("cp.async.commit_group;");
        }
        // ---- wait + restage B ----
        if (tid == 0) group_wait(grpB, genB);
        __syncthreads();
        {
            int b = tid >> 7, k = (tid & 127) << 2;
            const float* src = &g_Hbuf[t & 1][grpB][0];
            cp16(smem_u32(HsB + b * BHSTR + (k >> 5) * CHPAD + (k & 31)),
                 src + b * HIDDEN + k);
            asm volatile("cp.async.commit_group;");
            asm volatile("cp.async.wait_group 0;");
        }
        __syncthreads();
        ++genA; ++genB;
    }
}

// ---------------------------------------------------------------------------
extern "C" void kernel_launch(void* const* d_in, const int* in_sizes, int n_in,
                              void* d_out, int out_size)
{
    (void)in_sizes; (void)n_in; (void)out_size;
    const float* inputs = (const float*)d_in[0];
    const float* H      = (const float*)d_in[1];
    const float* W_net  = (const float*)d_in[2];
    const float* b_net  = (const float*)d_in[3];
    const float* W_deep = (const float*)d_in[4];
    const float* b_deep = (const float*)d_in[5];

    float* out     = (float*)d_out;
    float* states1 = out;
    float* lasts   = out + (size_t)T_STEPS * BATCH * HIDDEN;

    float *P, *S0;
    cudaGetSymbolAddress((void**)&P,  g_P);
    cudaGetSymbolAddress((void**)&S0, g_S0);

    cudaFuncSetAttribute(rnn_rec, cudaFuncAttributeMaxDynamicSharedMemorySize, REC_SMEM);

    dim3 ggrid(HIDDEN / 128, (T_STEPS * BATCH) / 128);

    gemm_awt<<<ggrid, 256>>>(inputs, W_net, b_net, P, VDIM, VDIM + HIDDEN);
    rnn_rec<<<NB, RT, REC_SMEM>>>(P, W_net, VDIM + HIDDEN, VDIM, H, S0, lasts);

    gemm_awt<<<ggrid, 256>>>(S0, W_deep, b_deep, P, HIDDEN, 2 * HIDDEN);
    rnn_rec<<<NB, RT, REC_SMEM>>>(P, W_deep, 2 * HIDDEN, HIDDEN,
                                  H + BATCH * HIDDEN, states1,
                                  lasts + BATCH * HIDDEN);
}

// round 12
// speedup vs baseline: 1.7301x; 1.7301x over previous
#include <cuda_runtime.h>
#include <math.h>
#include <stdint.h>

#define T_STEPS 1024
#define BATCH   64
#define VDIM    256
#define HIDDEN  512
#define CPB     64                 // columns per CTA
#define BG      4                  // batches per group
#define CBLKS   8                  // CTAs per group
#define GROUPS  16                 // batch groups
#define NB      128                // CTAs
#define RT      256
#define PSTR    21                 // partials row stride (16 data + 5 pad)
#define REC_SMEM (120 * 1024)      // force 1 CTA/SM

// Scratch (device globals: allocation APIs are forbidden)
__device__ float g_P [(size_t)T_STEPS * BATCH * HIDDEN];
__device__ float g_S0[(size_t)T_STEPS * BATCH * HIDDEN];
__device__ float g_Hbuf[2][GROUPS][BG * HIDDEN];

struct PadU { unsigned v; unsigned pad[63]; };
__device__ PadU g_count[GROUPS];
__device__ PadU g_gen[GROUPS];

#define FMA2(acc, w, h) \
    asm("fma.rn.f32x2 %0, %1, %2, %0;" : "+l"(acc) : "l"(w), "l"(h))
#define PACKF2(d, x) \
    asm("mov.b64 %0, {%1, %1};" : "=l"(d) : "f"(x))

// ---------------------------------------------------------------------------
// GEMM (f32x2): C[m][n] = sum_k A[m][k]*W[n*ldw+k] + bias[n]
// ---------------------------------------------------------------------------
__global__ __launch_bounds__(256) void gemm_awt(
    const float* __restrict__ A, const float* __restrict__ W,
    const float* __restrict__ bias, float* __restrict__ C,
    int K, int ldw)
{
    __shared__ float As[8][128];
    __shared__ float Ws[8][128];

    const int tid = threadIdx.x;
    const int m0 = blockIdx.y * 128;
    const int n0 = blockIdx.x * 128;
    const int tx = tid & 15;
    const int ty = tid >> 4;
    const int rowL = tid >> 1;
    const int colL = (tid & 1) * 4;

    const float* Ag = A + (size_t)(m0 + rowL) * K + colL;
    const float* Wg = W + (size_t)(n0 + rowL) * ldw + colL;

    long long accp[8][4];
#pragma unroll
    for (int i = 0; i < 8; ++i)
#pragma unroll
        for (int jp = 0; jp < 4; ++jp) accp[i][jp] = 0;

    float4 av = *(const float4*)(Ag);
    float4 wv = *(const float4*)(Wg);

    for (int k0 = 0; k0 < K; k0 += 8) {
        __syncthreads();
        As[colL + 0][rowL] = av.x; As[colL + 1][rowL] = av.y;
        As[colL + 2][rowL] = av.z; As[colL + 3][rowL] = av.w;
        Ws[colL + 0][rowL] = wv.x; Ws[colL + 1][rowL] = wv.y;
        Ws[colL + 2][rowL] = wv.z; Ws[colL + 3][rowL] = wv.w;
        __syncthreads();
        if (k0 + 8 < K) {
            av = *(const float4*)(Ag + k0 + 8);
            wv = *(const float4*)(Wg + k0 + 8);
        }
#pragma unroll
        for (int k = 0; k < 8; ++k) {
            float4 a0 = *(const float4*)&As[k][ty * 8];
            float4 a1 = *(const float4*)&As[k][ty * 8 + 4];
            longlong2 b01 = *(const longlong2*)&Ws[k][tx * 8];
            longlong2 b23 = *(const longlong2*)&Ws[k][tx * 8 + 4];
            float a[8] = {a0.x, a0.y, a0.z, a0.w, a1.x, a1.y, a1.z, a1.w};
#pragma unroll
            for (int i = 0; i < 8; ++i) {
                long long a2; PACKF2(a2, a[i]);
                FMA2(accp[i][0], a2, b01.x);
                FMA2(accp[i][1], a2, b01.y);
                FMA2(accp[i][2], a2, b23.x);
                FMA2(accp[i][3], a2, b23.y);
            }
        }
    }

    float bn[8];
#pragma unroll
    for (int j = 0; j < 8; ++j) bn[j] = bias[n0 + tx * 8 + j];

    float* Cp = C + (size_t)(m0 + ty * 8) * HIDDEN + n0 + tx * 8;
#pragma unroll
    for (int i = 0; i < 8; ++i) {
        float4 v0, v1;
        float2 f0 = *reinterpret_cast<float2*>(&accp[i][0]);
        float2 f1 = *reinterpret_cast<float2*>(&accp[i][1]);
        float2 f2 = *reinterpret_cast<float2*>(&accp[i][2]);
        float2 f3 = *reinterpret_cast<float2*>(&accp[i][3]);
        v0.x = f0.x + bn[0]; v0.y = f0.y + bn[1];
        v0.z = f1.x + bn[2]; v0.w = f1.y + bn[3];
        v1.x = f2.x + bn[4]; v1.y = f2.y + bn[5];
        v1.z = f3.x + bn[6]; v1.w = f3.y + bn[7];
        *(float4*)(Cp + (size_t)i * HIDDEN)     = v0;
        *(float4*)(Cp + (size_t)i * HIDDEN + 4) = v1;
    }
}

// ---------------------------------------------------------------------------
// Persistent recurrence, register-h version (no smem h at all):
//   thread: kc = tid>>4 (warp-uniform 32-wide k-chunk), jg = tid&15.
//   w[4 cols][32 k] in registers; h loaded per step straight from L2
//   (__ldcg, half-warp broadcast-coalesced); partial reduce via padded smem.
//   Exchange: STG h -> fence -> atomic arrive -> all-thread acquire poll.
// ---------------------------------------------------------------------------
__global__ __launch_bounds__(RT, 1) void rnn_rec(
    const float* __restrict__ P,
    const float* __restrict__ Wfull, int ldw, int koff,
    const float* __restrict__ h0,
    float* __restrict__ states,
    float* __restrict__ last)
{
    extern __shared__ float sh[];
    float* Ps = sh;                        // [256][PSTR]

    const int tid  = threadIdx.x;
    const int cblk = blockIdx.x & (CBLKS - 1);
    const int grp  = blockIdx.x >> 3;
    const int j0   = cblk * CPB;
    const int kc   = tid >> 4;             // 0..15 (uniform per half-warp)
    const int jg   = tid & 15;             // 0..15
    const int rb   = tid >> 6;             // reduce role: batch 0..3
    const int rcol = tid & 63;
    const int rj   = j0 + rcol;
    const int rbg  = grp * BG + rb;

    // Weights in registers: rows j0 + jg*4 + c, k = kc*32 .. +32.
    union LLF { float4 f; longlong2 l; };
    longlong2 wr[4][8];
#pragma unroll
    for (int c = 0; c < 4; ++c) {
        const float* wp = Wfull + (size_t)(j0 + jg * 4 + c) * ldw + koff + kc * 32;
#pragma unroll
        for (int i = 0; i < 8; ++i) {
            LLF u; u.f = *(const float4*)(wp + i * 4);
            wr[c][i] = u.l;
        }
    }

    // Publish our 64-col slice of h0 into buffer 1 (read at t=0).
    unsigned gen = *(volatile unsigned*)&g_gen[grp].v;   // before any arrive
    g_Hbuf[1][grp][rb * HIDDEN + rj] = h0[(size_t)rbg * HIDDEN + rj];
    __threadfence();
    __syncthreads();
    if (tid == 0) {
        unsigned tk = atomicAdd(&g_count[grp].v, 1u);
        if (tk == CBLKS - 1u) {
            *(volatile unsigned*)&g_count[grp].v = 0u;
            __threadfence();
            *(volatile unsigned*)&g_gen[grp].v = gen + 1u;
        }
    }

    for (int t = 0; t < T_STEPS; ++t) {
        float p = P[((size_t)t * BATCH + rbg) * HIDDEN + rj];  // before poll

        // All threads: acquire-poll the group generation.
        {
            unsigned cur;
            do {
                asm volatile("ld.acquire.gpu.u32 %0, [%1];"
                             : "=r"(cur) : "l"(&g_gen[grp].v) : "memory");
            } while (cur == gen);
            gen = cur;
        }

        // h_{t-1} straight from L2 into registers; 2 batches at a time.
        const float* hc = &g_Hbuf[(t + 1) & 1][grp][kc * 32];
        long long acc[4][4];
#pragma unroll
        for (int c = 0; c < 4; ++c)
#pragma unroll
            for (int b = 0; b < 4; ++b) acc[c][b] = 0;

#pragma unroll
        for (int pr = 0; pr < 2; ++pr) {
            LLF h[2][8];
#pragma unroll
            for (int b = 0; b < 2; ++b)
#pragma unroll
                for (int i = 0; i < 8; ++i)
                    h[b][i].f = __ldcg((const float4*)(hc + (pr * 2 + b) * HIDDEN + i * 4));
#pragma unroll
            for (int i = 0; i < 8; ++i)
#pragma unroll
                for (int c = 0; c < 4; ++c) {
                    longlong2 w = wr[c][i];
                    FMA2(acc[c][pr * 2 + 0], w.x, h[0][i].l.x);
                    FMA2(acc[c][pr * 2 + 0], w.y, h[0][i].l.y);
                    FMA2(acc[c][pr * 2 + 1], w.x, h[1][i].l.x);
                    FMA2(acc[c][pr * 2 + 1], w.y, h[1][i].l.y);
                }
        }

        // Partials to smem: out o = b*64 + jg*4 + c.
#pragma unroll
        for (int c = 0; c < 4; ++c)
#pragma unroll
            for (int b = 0; b < 4; ++b) {
                float2 f = *reinterpret_cast<float2*>(&acc[c][b]);
                Ps[(b * 64 + jg * 4 + c) * PSTR + kc] = f.x + f.y;
            }
        __syncthreads();

        // Reduce: thread owns output (rb, rcol).
        float s = 0.f;
        const float* pr2 = Ps + tid * PSTR;
#pragma unroll
        for (int i = 0; i < 16; ++i) s += pr2[i];
        float hv = tanhf(p + s);

        states[((size_t)t * BATCH + rbg) * HIDDEN + rj] = hv;
        if (t == T_STEPS - 1) {
            last[(size_t)rbg * HIDDEN + rj] = hv;
            break;
        }
        g_Hbuf[t & 1][grp][rb * HIDDEN + rj] = hv;

        __threadfence();
        __syncthreads();     // also protects Ps reuse next iteration
        if (tid == 0) {
            unsigned tk = atomicAdd(&g_count[grp].v, 1u);
            if (tk == CBLKS - 1u) {
                *(volatile unsigned*)&g_count[grp].v = 0u;
                __threadfence();
                *(volatile unsigned*)&g_gen[grp].v = gen + 1u;
            }
        }
    }
}

// ---------------------------------------------------------------------------
extern "C" void kernel_launch(void* const* d_in, const int* in_sizes, int n_in,
                              void* d_out, int out_size)
{
    (void)in_sizes; (void)n_in; (void)out_size;
    const float* inputs = (const float*)d_in[0];
    const float* H      = (const float*)d_in[1];
    const float* W_net  = (const float*)d_in[2];
    const float* b_net  = (const float*)d_in[3];
    const float* W_deep = (const float*)d_in[4];
    const float* b_deep = (const float*)d_in[5];

    float* out     = (float*)d_out;
    float* states1 = out;
    float* lasts   = out + (size_t)T_STEPS * BATCH * HIDDEN;

    float *P, *S0;
    cudaGetSymbolAddress((void**)&P,  g_P);
    cudaGetSymbolAddress((void**)&S0, g_S0);

    cudaFuncSetAttribute(rnn_rec, cudaFuncAttributeMaxDynamicSharedMemorySize, REC_SMEM);

    dim3 ggrid(HIDDEN / 128, (T_STEPS * BATCH) / 128);

    gemm_awt<<<ggrid, 256>>>(inputs, W_net, b_net, P, VDIM, VDIM + HIDDEN);
    rnn_rec<<<NB, RT, REC_SMEM>>>(P, W_net, VDIM + HIDDEN, VDIM, H, S0, lasts);

    gemm_awt<<<ggrid, 256>>>(S0, W_deep, b_deep, P, HIDDEN, 2 * HIDDEN);
    rnn_rec<<<NB, RT, REC_SMEM>>>(P, W_deep, 2 * HIDDEN, HIDDEN,
                                  H + BATCH * HIDDEN, states1,
                                  lasts + BATCH * HIDDEN);
}